// round 7
// baseline (speedup 1.0000x reference)
#include <cuda_runtime.h>
#include <cuda_bf16.h>

#define QN 64
#define AN 32
#define BN 256
#define SN 2048
#define MAXSTEP 520

// Interleaved bf16 layout for a 64x64 matrix W: element (i,j) at
//   bf16 index  (i>>3)*512 + j*8 + (i&7)
// One 16B granule = rows 8c..8c+7 of column j.
__device__ __align__(16) static __nv_bfloat16 g_pairs  [1024 * 4096];  // P[a0*32+a1]
__device__ __align__(16) static __nv_bfloat16 g_pairsT [1024 * 4096];  // P^T
__device__ __align__(16) static __nv_bfloat16 g_singles [32 * 4096];   // W[a]
__device__ __align__(16) static __nv_bfloat16 g_singlesT[32 * 4096];   // W[a]^T
__device__ __align__(16) static float g_Wf[32 * 4096];                 // f32 W[a]
__device__ static short g_order[BN];                                   // ids, desc length

// ---------------------------------------------------------------------------
// Kernel 1: W[a][i][j] = softmax_j(T_logits[i][a][:]). One warp per (i,a).
// ---------------------------------------------------------------------------
__global__ void k_softmax(const float* __restrict__ T) {
    int warp = (blockIdx.x << 2) + (threadIdx.x >> 5);   // warp = i*32 + a
    int lane = threadIdx.x & 31;
    int i = warp >> 5, a = warp & 31;
    const float* row = T + warp * 64;
    float v0 = row[lane], v1 = row[lane + 32];
    float m = fmaxf(v0, v1);
#pragma unroll
    for (int o = 16; o; o >>= 1) m = fmaxf(m, __shfl_xor_sync(0xFFFFFFFFu, m, o));
    float e0 = expf(v0 - m), e1 = expf(v1 - m);
    float s = e0 + e1;
#pragma unroll
    for (int o = 16; o; o >>= 1) s += __shfl_xor_sync(0xFFFFFFFFu, s, o);
    float inv = 1.0f / s;
    float w0 = e0 * inv, w1 = e1 * inv;

    float* wf = g_Wf + a * 4096 + i * 64;
    wf[lane] = w0;
    wf[lane + 32] = w1;

    __nv_bfloat16* sg  = g_singles  + a * 4096;
    __nv_bfloat16* sgT = g_singlesT + a * 4096;
    int c = i >> 3, r = i & 7;
    int j0 = lane, j1 = lane + 32;
    sg[c * 512 + j0 * 8 + r] = __float2bfloat16(w0);
    sg[c * 512 + j1 * 8 + r] = __float2bfloat16(w1);
    sgT[(j0 >> 3) * 512 + i * 8 + (j0 & 7)] = __float2bfloat16(w0);
    sgT[(j1 >> 3) * 512 + i * 8 + (j1 & 7)] = __float2bfloat16(w1);
}

// ---------------------------------------------------------------------------
// Kernel 1b: rank-sort sequence ids by length descending.
// ---------------------------------------------------------------------------
__global__ void k_sort(const int* __restrict__ lengths) {
    __shared__ int Ls[BN];
    int t = threadIdx.x;
    int L = lengths[t];
    Ls[t] = L;
    __syncthreads();
    int rank = 0;
#pragma unroll 8
    for (int i = 0; i < BN; i++) {
        int Li = Ls[i];
        rank += (Li > L) || (Li == L && i < t);
    }
    g_order[rank] = (short)t;
}

// ---------------------------------------------------------------------------
// Kernel 2: P = W[a0]@W[a1]; writes bf16 interleaved P AND P^T.
// 1024 CTAs x 128 threads, 8x4 register tiles, smem round-trip for transpose.
// ---------------------------------------------------------------------------
__device__ __forceinline__ unsigned packbf(float a, float b) {
    __nv_bfloat162 h = __floats2bfloat162_rn(a, b);
    return *(unsigned*)&h;
}

__global__ void k_pairs() {
    __shared__ __align__(16) float As[64][68];   // As[k][i] = A[i][k]; reused as Out[i][j]
    __shared__ __align__(16) float Bs[64][64];   // Bs[k][j] = B[k][j]
    int mId = blockIdx.x;
    int a0 = mId >> 5, a1 = mId & 31;
    const float* A  = g_Wf + a0 * 4096;
    const float* Bm = g_Wf + a1 * 4096;
    int t = threadIdx.x;
    for (int idx = t; idx < 4096; idx += 128) {
        As[idx & 63][idx >> 6] = A[idx];
        Bs[idx >> 6][idx & 63] = Bm[idx];
    }
    __syncthreads();

    int i0 = (t >> 4) << 3, j0 = (t & 15) << 2;   // 8 rows x 4 cols per thread
    float acc[8][4];
#pragma unroll
    for (int r = 0; r < 8; r++)
#pragma unroll
        for (int c = 0; c < 4; c++) acc[r][c] = 0.f;

    for (int k = 0; k < 64; k++) {
        float av[8];
        *(float4*)(av)     = *(const float4*)&As[k][i0];
        *(float4*)(av + 4) = *(const float4*)&As[k][i0 + 4];
        float4 bv = *(const float4*)&Bs[k][j0];
#pragma unroll
        for (int r = 0; r < 8; r++) {
            acc[r][0] = fmaf(av[r], bv.x, acc[r][0]);
            acc[r][1] = fmaf(av[r], bv.y, acc[r][1]);
            acc[r][2] = fmaf(av[r], bv.z, acc[r][2]);
            acc[r][3] = fmaf(av[r], bv.w, acc[r][3]);
        }
    }
    __syncthreads();
#pragma unroll
    for (int r = 0; r < 8; r++)
#pragma unroll
        for (int c = 0; c < 4; c++) As[i0 + r][j0 + c] = acc[r][c];
    __syncthreads();

    __nv_bfloat16* dstN = g_pairs  + mId * 4096;
    __nv_bfloat16* dstT = g_pairsT + mId * 4096;
#pragma unroll
    for (int q = 0; q < 4; q++) {
        int g = t + 128 * q;              // granule id 0..511
        int c = g >> 6, j = g & 63;
        uint4 u;
        u.x = packbf(As[8 * c + 0][j], As[8 * c + 1][j]);
        u.y = packbf(As[8 * c + 2][j], As[8 * c + 3][j]);
        u.z = packbf(As[8 * c + 4][j], As[8 * c + 5][j]);
        u.w = packbf(As[8 * c + 6][j], As[8 * c + 7][j]);
        *(uint4*)(dstN + c * 512 + j * 8) = u;
        int i = g & 63, cT = g >> 6;
        const float* rp = &As[i][8 * cT];
        uint4 v;
        v.x = packbf(rp[0], rp[1]);
        v.y = packbf(rp[2], rp[3]);
        v.z = packbf(rp[4], rp[5]);
        v.w = packbf(rp[6], rp[7]);
        *(uint4*)(dstT + cT * 512 + i * 8) = v;
    }
}

// ---------------------------------------------------------------------------
// Kernel 3: FUSED bidirectional forward. 148 CTAs x 128 threads = 2 slots of
// 64 threads; each slot runs ONE sequence with BOTH directions fused into the
// same threads (thread g owns column g of left alpha AND of right r). One
// 64-thread named barrier per fused step; both chains advance per step.
// Static pairing: slot0 = rank cta (long), slot1 = rank 255-cta (short).
// ---------------------------------------------------------------------------
__device__ __forceinline__ void ffma2(unsigned long long& acc, unsigned u,
                                      unsigned long long p2) {
    asm("{\n\t"
        ".reg .b32 wl, wh;\n\t"
        ".reg .b64 w2;\n\t"
        "shl.b32 wl, %1, 16;\n\t"
        "and.b32 wh, %1, 0xFFFF0000;\n\t"
        "mov.b64 w2, {wl, wh};\n\t"
        "fma.rn.f32x2 %0, w2, %2, %0;\n\t"
        "}" : "+l"(acc) : "r"(u), "l"(p2));
}
__device__ __forceinline__ unsigned long long addx2(unsigned long long a,
                                                    unsigned long long b) {
    unsigned long long r;
    asm("add.rn.f32x2 %0, %1, %2;" : "=l"(r) : "l"(a), "l"(b));
    return r;
}
__device__ __forceinline__ void unpack2(unsigned long long a, float& lo, float& hi) {
    asm("mov.b64 {%0, %1}, %2;" : "=f"(lo), "=f"(hi) : "l"(a));
}

// Load one direction's 8 granules for step T_ into W.
#define LOADW(W, MIDX, PAIRS, SINGLES)                                         \
    {                                                                          \
        int off_ = (MIDX);                                                     \
        const uint4* b_ =                                                      \
            ((off_ & 1) ? (SINGLES) : (PAIRS)) + ((off_ & ~1) >> 3) + g;       \
        _Pragma("unroll")                                                      \
        for (int c_ = 0; c_ < 8; c_++) (W)[c_] = __ldg(b_ + c_ * 64);          \
    }

// One fused step: advances left (if t < nL) and right (if t < nR).
#define FSTEP(WL, WR)                                                          \
    {                                                                          \
        const ulonglong2* pcL_ = (const ulonglong2*)pLs[t & 1];                \
        const ulonglong2* pcR_ = (const ulonglong2*)pRs[t & 1];                \
        unsigned long long A_ = 0ull, B_ = 0ull, C_ = 0ull, D_ = 0ull;         \
        unsigned long long E_ = 0ull, F_ = 0ull, G_ = 0ull, H_ = 0ull;         \
        _Pragma("unroll")                                                      \
        for (int c_ = 0; c_ < 8; c_++) {                                       \
            ulonglong2 l0_ = pcL_[2 * c_];                                     \
            ulonglong2 l1_ = pcL_[2 * c_ + 1];                                 \
            ulonglong2 r0_ = pcR_[2 * c_];                                     \
            ulonglong2 r1_ = pcR_[2 * c_ + 1];                                 \
            uint4 uL_ = (WL)[c_];                                              \
            uint4 uR_ = (WR)[c_];                                              \
            ffma2(A_, uL_.x, l0_.x);  ffma2(E_, uR_.x, r0_.x);                 \
            ffma2(B_, uL_.y, l0_.y);  ffma2(F_, uR_.y, r0_.y);                 \
            ffma2(C_, uL_.z, l1_.x);  ffma2(G_, uR_.z, r1_.x);                 \
            ffma2(D_, uL_.w, l1_.y);  ffma2(H_, uR_.w, r1_.y);                 \
        }                                                                      \
        if (t + 2 < nL) LOADW(WL, midxL[t + 2], pairsN, singlesN);             \
        if (t + 2 < nR) LOADW(WR, midxR[t + 2], pairsT, singlesT);             \
        A_ = addx2(A_, B_); C_ = addx2(C_, D_); A_ = addx2(A_, C_);            \
        E_ = addx2(E_, F_); G_ = addx2(G_, H_); E_ = addx2(E_, G_);            \
        float lo_, hi_;                                                        \
        unpack2(A_, lo_, hi_);                                                 \
        if (t < nL) pLs[(t + 1) & 1][g] = lo_ + hi_;                           \
        unpack2(E_, lo_, hi_);                                                 \
        if (t < nR) pRs[(t + 1) & 1][g] = lo_ + hi_;                           \
        asm volatile("bar.sync %0, 64;" :: "r"(barid) : "memory");             \
        t++;                                                                   \
    }

__global__ void __launch_bounds__(128, 1)
k_forward(const int* __restrict__ x, const int* __restrict__ lengths,
          const float* __restrict__ f_logits, float* __restrict__ out) {
    __shared__ __align__(16) float pL[2][2][QN];   // [slot][buf][col]
    __shared__ __align__(16) float pR[2][2][QN];
    __shared__ __align__(16) float ef[QN];         // exp(f - M)
    __shared__ int midxA[2][MAXSTEP];              // [slot] left
    __shared__ int midxB[2][MAXSTEP];              // [slot] right
    __shared__ float red[2][4];
    __shared__ float prep[4];
    __shared__ float sLogS2;

    int tid = threadIdx.x;

    // ---- hoisted f_logits prep (warps 0-1 only) ----
    if (tid < 64) {
        float f = __ldg(f_logits + tid);
        float Mv = f;
#pragma unroll
        for (int o = 16; o; o >>= 1) Mv = fmaxf(Mv, __shfl_xor_sync(0xFFFFFFFFu, Mv, o));
        if ((tid & 31) == 0) prep[tid >> 5] = Mv;
        asm volatile("bar.sync 7, 64;" ::: "memory");
        float M = fmaxf(prep[0], prep[1]);
        float e = expf(f - M);
        ef[tid] = e;
        float S2 = e;
#pragma unroll
        for (int o = 16; o; o >>= 1) S2 += __shfl_xor_sync(0xFFFFFFFFu, S2, o);
        if ((tid & 31) == 0) prep[2 + (tid >> 5)] = S2;
        asm volatile("bar.sync 7, 64;" ::: "memory");
        if (tid == 0) sLogS2 = logf(prep[2] + prep[3]);
    }
    __syncthreads();

    // ---- static assignment: slot0 = rank cta, slot1 = rank 255-cta ----
    int slot = tid >> 6;            // 0 or 1
    int g = tid & 63;               // thread within slot = column index
    int cta = blockIdx.x;
    int rank = slot == 0 ? cta : (BN - 1 - cta);
    if (slot == 1 && rank < 148) return;          // no second sequence
    int b = g_order[rank];
    int barid = 1 + slot;

    int L = __ldg(lengths + b);
    int np  = L >> 1;
    int nL  = (np + 1) >> 1;        // left pair-steps
    int npR = np - nL;
    int odd = L & 1;
    int nR  = npR + odd;            // right steps (incl. odd single)
    int nmax = nL > nR ? nL : nR;
    int m = 2 * nL;
    const int* xb = x + b * SN;
    int* midxL = midxA[slot];
    int* midxR = midxB[slot];
    float (*pLs)[QN] = pL[slot];
    float (*pRs)[QN] = pR[slot];

    for (int t = g; t < nL; t += 64)
        midxL[t] = (__ldg(xb + 2 * t) * 32 + __ldg(xb + 2 * t + 1)) * 4096;
    for (int s2 = g; s2 < nR; s2 += 64) {
        int off;
        if (odd && s2 == 0) {
            off = __ldg(xb + L - 1) * 4096 | 1;
        } else {
            int k = npR - 1 - (s2 - odd);
            off = (__ldg(xb + m + 2 * k) * 32 + __ldg(xb + m + 2 * k + 1)) * 4096;
        }
        midxR[s2] = off;
    }
    pLs[0][g] = (g == 0) ? 1.0f : 0.0f;
    pRs[0][g] = ef[g];
    asm volatile("bar.sync %0, 64;" :: "r"(barid) : "memory");

    const uint4* pairsN   = (const uint4*)g_pairs;
    const uint4* singlesN = (const uint4*)g_singles;
    const uint4* pairsT   = (const uint4*)g_pairsT;
    const uint4* singlesT = (const uint4*)g_singlesT;

    uint4 wL0[8], wL1[8], wR0[8], wR1[8];
    if (0 < nL) LOADW(wL0, midxL[0], pairsN, singlesN);
    if (1 < nL) LOADW(wL1, midxL[1], pairsN, singlesN);
    if (0 < nR) LOADW(wR0, midxR[0], pairsT, singlesT);
    if (1 < nR) LOADW(wR1, midxR[1], pairsT, singlesT);

    int t = 0;
    while (t < nmax) {
        FSTEP(wL0, wR0);
        if (t >= nmax) break;
        FSTEP(wL1, wR1);
    }

    // ---- combine within the slot's 64 threads ----
    {
        int wid = g >> 5;
        float a = pLs[nL & 1][g];
        float r = pRs[nR & 1][g];
        float d = a * r, sa = a;
#pragma unroll
        for (int o = 16; o; o >>= 1) {
            d  += __shfl_xor_sync(0xFFFFFFFFu, d,  o);
            sa += __shfl_xor_sync(0xFFFFFFFFu, sa, o);
        }
        if ((g & 31) == 0) { red[slot][wid] = d; red[slot][2 + wid] = sa; }
        asm volatile("bar.sync %0, 64;" :: "r"(barid) : "memory");
        if (g == 0)
            out[b] = logf(red[slot][0] + red[slot][1])
                   - logf(red[slot][2] + red[slot][3]) - sLogS2;
    }
}

extern "C" void kernel_launch(void* const* d_in, const int* in_sizes, int n_in,
                              void* d_out, int out_size) {
    const int*   x        = (const int*)d_in[0];       // [256, 2048]
    const int*   lengths  = (const int*)d_in[1];       // [256]
    const float* T_logits = (const float*)d_in[2];     // [64, 32, 64]
    const float* f_logits = (const float*)d_in[3];     // [64]
    float* out = (float*)d_out;                        // [256]

    k_softmax<<<512, 128>>>(T_logits);
    k_sort<<<1, BN>>>(lengths);
    k_pairs<<<1024, 128>>>();
    k_forward<<<148, 128>>>(x, lengths, f_logits, out);
}

// round 10
// speedup vs baseline: 1.0324x; 1.0324x over previous
#include <cuda_runtime.h>
#include <cuda_bf16.h>

#define QN 64
#define AN 32
#define BN 256
#define SN 2048
#define MAXSTEP 520

// f32 interleaved layout for a 64x64 matrix W: element (i,j) at
//   f32 index  (i>>2)*256 + j*4 + (i&3)
// One 16B granule = rows 4c..4c+3 of column j; column j = 16 granules at
// stride 256 f32. Thread j's granule loads are 512B-contiguous per warp.
__device__ __align__(16) static float g_pairsF  [1024 * 4096];  // 16 MB
__device__ __align__(16) static float g_pairsTF [1024 * 4096];  // 16 MB
__device__ __align__(16) static float g_singlesF [32 * 4096];
__device__ __align__(16) static float g_singlesTF[32 * 4096];
__device__ __align__(16) static float g_Wf[32 * 4096];          // plain f32 W[a]
__device__ static short g_order[BN];                            // ids, desc length

// ---------------------------------------------------------------------------
// Kernel 1: W[a][i][j] = softmax_j(T_logits[i][a][:]). One warp per (i,a).
// ---------------------------------------------------------------------------
__global__ void k_softmax(const float* __restrict__ T) {
    int warp = (blockIdx.x << 2) + (threadIdx.x >> 5);   // warp = i*32 + a
    int lane = threadIdx.x & 31;
    int i = warp >> 5, a = warp & 31;
    const float* row = T + warp * 64;
    float v0 = row[lane], v1 = row[lane + 32];
    float m = fmaxf(v0, v1);
#pragma unroll
    for (int o = 16; o; o >>= 1) m = fmaxf(m, __shfl_xor_sync(0xFFFFFFFFu, m, o));
    float e0 = expf(v0 - m), e1 = expf(v1 - m);
    float s = e0 + e1;
#pragma unroll
    for (int o = 16; o; o >>= 1) s += __shfl_xor_sync(0xFFFFFFFFu, s, o);
    float inv = 1.0f / s;
    float w0 = e0 * inv, w1 = e1 * inv;

    float* wf = g_Wf + a * 4096 + i * 64;
    wf[lane] = w0;
    wf[lane + 32] = w1;

    float* sg  = g_singlesF  + a * 4096;
    float* sgT = g_singlesTF + a * 4096;
    int j0 = lane, j1 = lane + 32;
    // normal: (i, j)
    sg[(i >> 2) * 256 + j0 * 4 + (i & 3)] = w0;
    sg[(i >> 2) * 256 + j1 * 4 + (i & 3)] = w1;
    // transposed: (j, i)
    sgT[(j0 >> 2) * 256 + i * 4 + (j0 & 3)] = w0;
    sgT[(j1 >> 2) * 256 + i * 4 + (j1 & 3)] = w1;
}

// ---------------------------------------------------------------------------
// Kernel 1b: rank-sort sequence ids by length descending.
// ---------------------------------------------------------------------------
__global__ void k_sort(const int* __restrict__ lengths) {
    __shared__ int Ls[BN];
    int t = threadIdx.x;
    int L = lengths[t];
    Ls[t] = L;
    __syncthreads();
    int rank = 0;
#pragma unroll 8
    for (int i = 0; i < BN; i++) {
        int Li = Ls[i];
        rank += (Li > L) || (Li == L && i < t);
    }
    g_order[rank] = (short)t;
}

// ---------------------------------------------------------------------------
// Kernel 2: P = W[a0]@W[a1]; writes f32 interleaved P AND P^T.
// 1024 CTAs x 128 threads, 8x4 register tiles, smem round-trip for emission.
// ---------------------------------------------------------------------------
__global__ void k_pairs() {
    __shared__ __align__(16) float As[64][68];   // As[k][i] = A[i][k]; reused Out[i][j]
    __shared__ __align__(16) float Bs[64][64];   // Bs[k][j] = B[k][j]
    int mId = blockIdx.x;
    int a0 = mId >> 5, a1 = mId & 31;
    const float* A  = g_Wf + a0 * 4096;
    const float* Bm = g_Wf + a1 * 4096;
    int t = threadIdx.x;
    for (int idx = t; idx < 4096; idx += 128) {
        As[idx & 63][idx >> 6] = A[idx];
        Bs[idx >> 6][idx & 63] = Bm[idx];
    }
    __syncthreads();

    int i0 = (t >> 4) << 3, j0 = (t & 15) << 2;   // 8 rows x 4 cols per thread
    float acc[8][4];
#pragma unroll
    for (int r = 0; r < 8; r++)
#pragma unroll
        for (int c = 0; c < 4; c++) acc[r][c] = 0.f;

    for (int k = 0; k < 64; k++) {
        float av[8];
        *(float4*)(av)     = *(const float4*)&As[k][i0];
        *(float4*)(av + 4) = *(const float4*)&As[k][i0 + 4];
        float4 bv = *(const float4*)&Bs[k][j0];
#pragma unroll
        for (int r = 0; r < 8; r++) {
            acc[r][0] = fmaf(av[r], bv.x, acc[r][0]);
            acc[r][1] = fmaf(av[r], bv.y, acc[r][1]);
            acc[r][2] = fmaf(av[r], bv.z, acc[r][2]);
            acc[r][3] = fmaf(av[r], bv.w, acc[r][3]);
        }
    }
    __syncthreads();
#pragma unroll
    for (int r = 0; r < 8; r++)
#pragma unroll
        for (int c = 0; c < 4; c++) As[i0 + r][j0 + c] = acc[r][c];
    __syncthreads();

    float* dstN = g_pairsF  + mId * 4096;
    float* dstT = g_pairsTF + mId * 4096;
#pragma unroll
    for (int q = 0; q < 8; q++) {
        int gidx = t + 128 * q;            // granule id 0..1023
        int c = gidx >> 6, j = gidx & 63;
        float4 v;
        v.x = As[4 * c + 0][j];
        v.y = As[4 * c + 1][j];
        v.z = As[4 * c + 2][j];
        v.w = As[4 * c + 3][j];
        *(float4*)(dstN + c * 256 + j * 4) = v;
        // transposed granule: PT rows 4c..4c+3 of col j = P[j][4c..4c+3] contiguous
        float4 vt = *(const float4*)&As[j][4 * c];
        *(float4*)(dstT + c * 256 + j * 4) = vt;
    }
}

// ---------------------------------------------------------------------------
// Kernel 3: bidirectional forward, 2 sequences per CTA (long<->short static
// pairing). 148 CTAs x 256 threads = 4 independent 64-thread groups:
//   tid   0- 63: seqA left (bar1)   tid  64-127: seqA right (bar2)
//   tid 128-191: seqB left (bar3)   tid 192-255: seqB right (bar4)
// One thread per column; tables are f32 pairs -> inner op is ONE fma.rn.f32x2.
// midx padded with 2 dummy entries -> branchless unconditional prefetch.
// ---------------------------------------------------------------------------
__device__ __forceinline__ void fma2(unsigned long long& acc,
                                     unsigned long long w, unsigned long long p) {
    asm("fma.rn.f32x2 %0, %1, %2, %0;" : "+l"(acc) : "l"(w), "l"(p));
}
__device__ __forceinline__ unsigned long long addx2(unsigned long long a,
                                                    unsigned long long b) {
    unsigned long long r;
    asm("add.rn.f32x2 %0, %1, %2;" : "=l"(r) : "l"(a), "l"(b));
    return r;
}
__device__ __forceinline__ void unpack2(unsigned long long a, float& lo, float& hi) {
    asm("mov.b64 {%0, %1}, %2;" : "=f"(lo), "=f"(hi) : "l"(a));
}

// W = 16 granules (ulonglong2) of column g for the matrix at midx entry.
#define LOADW(W, MIDX)                                                         \
    {                                                                          \
        int off_ = (MIDX);                                                     \
        const ulonglong2* b_ =                                                 \
            ((off_ & 1) ? singles : pairs) + ((off_ & ~1) >> 2) + g;           \
        _Pragma("unroll")                                                      \
        for (int c_ = 0; c_ < 16; c_++) (W)[c_] = __ldg(b_ + c_ * 64);         \
    }

#define STEPD(W)                                                               \
    {                                                                          \
        const ulonglong2* pc_ = (const ulonglong2*)psm[t & 1];                 \
        unsigned long long A_ = 0ull, B_ = 0ull, C_ = 0ull, D_ = 0ull;         \
        _Pragma("unroll")                                                      \
        for (int c_ = 0; c_ < 8; c_++) {                                       \
            ulonglong2 p0_ = pc_[2 * c_];                                      \
            ulonglong2 p1_ = pc_[2 * c_ + 1];                                  \
            ulonglong2 w0_ = (W)[2 * c_];                                      \
            ulonglong2 w1_ = (W)[2 * c_ + 1];                                  \
            fma2(A_, w0_.x, p0_.x);                                            \
            fma2(B_, w0_.y, p0_.y);                                            \
            fma2(C_, w1_.x, p1_.x);                                            \
            fma2(D_, w1_.y, p1_.y);                                            \
        }                                                                      \
        LOADW(W, midx[t + 2]);                                                 \
        A_ = addx2(A_, B_);                                                    \
        C_ = addx2(C_, D_);                                                    \
        A_ = addx2(A_, C_);                                                    \
        float lo_, hi_;                                                        \
        unpack2(A_, lo_, hi_);                                                 \
        psm[(t + 1) & 1][g] = lo_ + hi_;                                       \
        asm volatile("bar.sync %0, 64;" :: "r"(barid) : "memory");             \
        t++;                                                                   \
    }

__device__ __forceinline__ void run_dir(const ulonglong2* __restrict__ pairs,
                                        const ulonglong2* __restrict__ singles,
                                        const int* midx, int nsteps,
                                        float (*psm)[QN], int g, int barid) {
    ulonglong2 w0[16], w1[16];
    LOADW(w0, midx[0]);
    LOADW(w1, midx[1]);
    int t = 0;
    while (t < nsteps) {
        STEPD(w0);
        if (t >= nsteps) break;
        STEPD(w1);
    }
}

__global__ void __launch_bounds__(256, 1)
k_forward(const int* __restrict__ x, const int* __restrict__ lengths,
          const float* __restrict__ f_logits, float* __restrict__ out) {
    __shared__ __align__(16) float pL[2][2][QN];   // [slot][buf][col]
    __shared__ __align__(16) float pR[2][2][QN];
    __shared__ __align__(16) float ef[QN];         // exp(f - M)
    __shared__ int midxA[2][MAXSTEP + 2];          // [slot] left  (padded)
    __shared__ int midxB[2][MAXSTEP + 2];          // [slot] right (padded)
    __shared__ float red[2][4];
    __shared__ float prep[4];
    __shared__ float sLogS2;

    int tid = threadIdx.x;

    // ---- hoisted f_logits prep (warps 0-1) ----
    if (tid < 64) {
        float f = __ldg(f_logits + tid);
        float Mv = f;
#pragma unroll
        for (int o = 16; o; o >>= 1) Mv = fmaxf(Mv, __shfl_xor_sync(0xFFFFFFFFu, Mv, o));
        if ((tid & 31) == 0) prep[tid >> 5] = Mv;
        asm volatile("bar.sync 7, 64;" ::: "memory");
        float M = fmaxf(prep[0], prep[1]);
        float e = expf(f - M);
        ef[tid] = e;
        float S2 = e;
#pragma unroll
        for (int o = 16; o; o >>= 1) S2 += __shfl_xor_sync(0xFFFFFFFFu, S2, o);
        if ((tid & 31) == 0) prep[2 + (tid >> 5)] = S2;
        asm volatile("bar.sync 7, 64;" ::: "memory");
        if (tid == 0) sLogS2 = logf(prep[2] + prep[3]);
    }
    __syncthreads();

    // ---- static assignment: slot0 = rank cta (long), slot1 = rank 255-cta ----
    int slot = tid >> 7;            // 0 or 1
    int tid7 = tid & 127;           // id within sequence group
    int cta = blockIdx.x;
    int rank = slot == 0 ? cta : (BN - 1 - cta);
    if (slot == 1 && rank < 148) return;          // no second sequence
    int b = g_order[rank];

    int L = __ldg(lengths + b);
    int np  = L >> 1;
    int nL  = (np + 1) >> 1;
    int npR = np - nL;
    int odd = L & 1;
    int nR  = npR + odd;
    int m = 2 * nL;
    const int* xb = x + b * SN;
    int* midxL = midxA[slot];
    int* midxR = midxB[slot];

    for (int t = tid7; t < nL; t += 128)
        midxL[t] = (__ldg(xb + 2 * t) * 32 + __ldg(xb + 2 * t + 1)) * 4096;
    for (int s2 = tid7; s2 < nR; s2 += 128) {
        int off;
        if (odd && s2 == 0) {
            off = __ldg(xb + L - 1) * 4096 | 1;
        } else {
            int k = npR - 1 - (s2 - odd);
            off = (__ldg(xb + m + 2 * k) * 32 + __ldg(xb + m + 2 * k + 1)) * 4096;
        }
        midxR[s2] = off;
    }
    if (tid7 < 2) {                                // pad for branchless prefetch
        midxL[nL + tid7] = 0;
        midxR[nR + tid7] = 0;
    }
    if (tid7 < 64) pL[slot][0][tid7] = (tid7 == 0) ? 1.0f : 0.0f;
    else           pR[slot][0][tid7 - 64] = ef[tid7 - 64];
    asm volatile("bar.sync %0, 128;" :: "r"(5 + slot) : "memory");

    int dir = tid7 >> 6;            // 0 = left, 1 = right
    int barid = 1 + 2 * slot + dir; // 1,2 (slot0), 3,4 (slot1)
    if (dir == 0)
        run_dir((const ulonglong2*)g_pairsF,  (const ulonglong2*)g_singlesF,
                midxL, nL, pL[slot], tid7, barid);
    else
        run_dir((const ulonglong2*)g_pairsTF, (const ulonglong2*)g_singlesTF,
                midxR, nR, pR[slot], tid7 - 64, barid);
    asm volatile("bar.sync %0, 128;" :: "r"(5 + slot) : "memory");

    // ---- combine (left group of each slot) ----
    if (tid7 < 64) {
        int wid = tid7 >> 5;
        float a = pL[slot][nL & 1][tid7];
        float r = pR[slot][nR & 1][tid7];
        float d = a * r, sa = a;
#pragma unroll
        for (int o = 16; o; o >>= 1) {
            d  += __shfl_xor_sync(0xFFFFFFFFu, d,  o);
            sa += __shfl_xor_sync(0xFFFFFFFFu, sa, o);
        }
        if ((tid7 & 31) == 0) { red[slot][wid] = d; red[slot][2 + wid] = sa; }
        asm volatile("bar.sync %0, 64;" :: "r"(1 + 2 * slot) : "memory");
        if (tid7 == 0)
            out[b] = logf(red[slot][0] + red[slot][1])
                   - logf(red[slot][2] + red[slot][3]) - sLogS2;
    }
}

extern "C" void kernel_launch(void* const* d_in, const int* in_sizes, int n_in,
                              void* d_out, int out_size) {
    const int*   x        = (const int*)d_in[0];       // [256, 2048]
    const int*   lengths  = (const int*)d_in[1];       // [256]
    const float* T_logits = (const float*)d_in[2];     // [64, 32, 64]
    const float* f_logits = (const float*)d_in[3];     // [64]
    float* out = (float*)d_out;                        // [256]

    k_softmax<<<512, 128>>>(T_logits);
    k_sort<<<1, BN>>>(lengths);
    k_pairs<<<1024, 128>>>();
    k_forward<<<148, 256>>>(x, lengths, f_logits, out);
}

// round 11
// speedup vs baseline: 1.4309x; 1.3860x over previous
#include <cuda_runtime.h>
#include <cuda_bf16.h>

#define QN 64
#define AN 32
#define BN 256
#define SN 2048
#define MAXSTEP 520

// Interleaved bf16 layout for a 64x64 matrix W: element (i,j) at
//   bf16 index  (i>>3)*512 + j*8 + (i&7)
// One 16B granule = rows 8c..8c+7 of column j.
__device__ __align__(16) static __nv_bfloat16 g_pairs  [1024 * 4096];  // P[a0*32+a1]
__device__ __align__(16) static __nv_bfloat16 g_pairsT [1024 * 4096];  // P^T
__device__ __align__(16) static __nv_bfloat16 g_singles [32 * 4096];   // W[a]
__device__ __align__(16) static __nv_bfloat16 g_singlesT[32 * 4096];   // W[a]^T
__device__ __align__(16) static float g_Wf[32 * 4096];                 // f32 W[a]
__device__ static short g_order[BN];                                   // ids, desc length

// ---------------------------------------------------------------------------
// Kernel 1: W[a][i][j] = softmax_j(T_logits[i][a][:]). One warp per (i,a).
// ---------------------------------------------------------------------------
__global__ void k_softmax(const float* __restrict__ T) {
    int warp = (blockIdx.x << 2) + (threadIdx.x >> 5);   // warp = i*32 + a
    int lane = threadIdx.x & 31;
    int i = warp >> 5, a = warp & 31;
    const float* row = T + warp * 64;
    float v0 = row[lane], v1 = row[lane + 32];
    float m = fmaxf(v0, v1);
#pragma unroll
    for (int o = 16; o; o >>= 1) m = fmaxf(m, __shfl_xor_sync(0xFFFFFFFFu, m, o));
    float e0 = expf(v0 - m), e1 = expf(v1 - m);
    float s = e0 + e1;
#pragma unroll
    for (int o = 16; o; o >>= 1) s += __shfl_xor_sync(0xFFFFFFFFu, s, o);
    float inv = 1.0f / s;
    float w0 = e0 * inv, w1 = e1 * inv;

    float* wf = g_Wf + a * 4096 + i * 64;
    wf[lane] = w0;
    wf[lane + 32] = w1;

    __nv_bfloat16* sg  = g_singles  + a * 4096;
    __nv_bfloat16* sgT = g_singlesT + a * 4096;
    int c = i >> 3, r = i & 7;
    int j0 = lane, j1 = lane + 32;
    sg[c * 512 + j0 * 8 + r] = __float2bfloat16(w0);
    sg[c * 512 + j1 * 8 + r] = __float2bfloat16(w1);
    sgT[(j0 >> 3) * 512 + i * 8 + (j0 & 7)] = __float2bfloat16(w0);
    sgT[(j1 >> 3) * 512 + i * 8 + (j1 & 7)] = __float2bfloat16(w1);
}

// ---------------------------------------------------------------------------
// Kernel 1b: rank-sort sequence ids by length descending.
// ---------------------------------------------------------------------------
__global__ void k_sort(const int* __restrict__ lengths) {
    __shared__ int Ls[BN];
    int t = threadIdx.x;
    int L = lengths[t];
    Ls[t] = L;
    __syncthreads();
    int rank = 0;
#pragma unroll 8
    for (int i = 0; i < BN; i++) {
        int Li = Ls[i];
        rank += (Li > L) || (Li == L && i < t);
    }
    g_order[rank] = (short)t;
}

// ---------------------------------------------------------------------------
// Kernel 2: P = W[a0]@W[a1]; writes bf16 interleaved P AND P^T.
// 1024 CTAs x 128 threads, 8x4 register tiles, smem round-trip for transpose.
// ---------------------------------------------------------------------------
__device__ __forceinline__ unsigned packbf(float a, float b) {
    __nv_bfloat162 h = __floats2bfloat162_rn(a, b);
    return *(unsigned*)&h;
}

__global__ void k_pairs() {
    __shared__ __align__(16) float As[64][68];   // As[k][i] = A[i][k]; reused as Out[i][j]
    __shared__ __align__(16) float Bs[64][64];   // Bs[k][j] = B[k][j]
    int mId = blockIdx.x;
    int a0 = mId >> 5, a1 = mId & 31;
    const float* A  = g_Wf + a0 * 4096;
    const float* Bm = g_Wf + a1 * 4096;
    int t = threadIdx.x;
    for (int idx = t; idx < 4096; idx += 128) {
        As[idx & 63][idx >> 6] = A[idx];
        Bs[idx >> 6][idx & 63] = Bm[idx];
    }
    __syncthreads();

    int i0 = (t >> 4) << 3, j0 = (t & 15) << 2;   // 8 rows x 4 cols per thread
    float acc[8][4];
#pragma unroll
    for (int r = 0; r < 8; r++)
#pragma unroll
        for (int c = 0; c < 4; c++) acc[r][c] = 0.f;

    for (int k = 0; k < 64; k++) {
        float av[8];
        *(float4*)(av)     = *(const float4*)&As[k][i0];
        *(float4*)(av + 4) = *(const float4*)&As[k][i0 + 4];
        float4 bv = *(const float4*)&Bs[k][j0];
#pragma unroll
        for (int r = 0; r < 8; r++) {
            acc[r][0] = fmaf(av[r], bv.x, acc[r][0]);
            acc[r][1] = fmaf(av[r], bv.y, acc[r][1]);
            acc[r][2] = fmaf(av[r], bv.z, acc[r][2]);
            acc[r][3] = fmaf(av[r], bv.w, acc[r][3]);
        }
    }
    __syncthreads();
#pragma unroll
    for (int r = 0; r < 8; r++)
#pragma unroll
        for (int c = 0; c < 4; c++) As[i0 + r][j0 + c] = acc[r][c];
    __syncthreads();

    __nv_bfloat16* dstN = g_pairs  + mId * 4096;
    __nv_bfloat16* dstT = g_pairsT + mId * 4096;
#pragma unroll
    for (int q = 0; q < 4; q++) {
        int g = t + 128 * q;              // granule id 0..511
        int c = g >> 6, j = g & 63;
        uint4 u;
        u.x = packbf(As[8 * c + 0][j], As[8 * c + 1][j]);
        u.y = packbf(As[8 * c + 2][j], As[8 * c + 3][j]);
        u.z = packbf(As[8 * c + 4][j], As[8 * c + 5][j]);
        u.w = packbf(As[8 * c + 6][j], As[8 * c + 7][j]);
        *(uint4*)(dstN + c * 512 + j * 8) = u;
        int i = g & 63, cT = g >> 6;
        const float* rp = &As[i][8 * cT];
        uint4 v;
        v.x = packbf(rp[0], rp[1]);
        v.y = packbf(rp[2], rp[3]);
        v.z = packbf(rp[4], rp[5]);
        v.w = packbf(rp[6], rp[7]);
        *(uint4*)(dstT + cT * 512 + i * 8) = v;
    }
}

// ---------------------------------------------------------------------------
// Kernel 3: bidirectional forward, 2 sequences per CTA (long<->short static
// pairing). 148 CTAs x 256 threads = 4 independent 64-thread groups:
//   tid   0- 63: seqA left (bar1)   tid  64-127: seqA right (bar2)
//   tid 128-191: seqB left (bar3)   tid 192-255: seqB right (bar4)
// One thread per column, 8 k-chunks, f32x2 packed math.
// Depth-3 register prefetch (w0/w1/w2) + 3-entry midx padding = branchless.
// ---------------------------------------------------------------------------
__device__ __forceinline__ void ffma2(unsigned long long& acc, unsigned u,
                                      unsigned long long p2) {
    asm("{\n\t"
        ".reg .b32 wl, wh;\n\t"
        ".reg .b64 w2;\n\t"
        "shl.b32 wl, %1, 16;\n\t"
        "and.b32 wh, %1, 0xFFFF0000;\n\t"
        "mov.b64 w2, {wl, wh};\n\t"
        "fma.rn.f32x2 %0, w2, %2, %0;\n\t"
        "}" : "+l"(acc) : "r"(u), "l"(p2));
}
__device__ __forceinline__ unsigned long long addx2(unsigned long long a,
                                                    unsigned long long b) {
    unsigned long long r;
    asm("add.rn.f32x2 %0, %1, %2;" : "=l"(r) : "l"(a), "l"(b));
    return r;
}
__device__ __forceinline__ void unpack2(unsigned long long a, float& lo, float& hi) {
    asm("mov.b64 {%0, %1}, %2;" : "=f"(lo), "=f"(hi) : "l"(a));
}

#define LOADW(W, MIDX)                                                         \
    {                                                                          \
        int off_ = (MIDX);                                                     \
        const uint4* b_ =                                                      \
            ((off_ & 1) ? singles : pairs) + ((off_ & ~1) >> 3) + j;           \
        _Pragma("unroll")                                                      \
        for (int c_ = 0; c_ < 8; c_++) (W)[c_] = __ldg(b_ + c_ * 64);          \
    }

// Step: LDS p, fma, unconditional depth-3 prefetch, STS, bar.
#define STEPD(W)                                                               \
    {                                                                          \
        const ulonglong2* pc_ = (const ulonglong2*)psm[t & 1];                 \
        unsigned long long A_ = 0ull, B_ = 0ull, C_ = 0ull, D_ = 0ull;         \
        _Pragma("unroll")                                                      \
        for (int c_ = 0; c_ < 8; c_++) {                                       \
            ulonglong2 p0_ = pc_[2 * c_];                                      \
            ulonglong2 p1_ = pc_[2 * c_ + 1];                                  \
            uint4 u_ = (W)[c_];                                                \
            ffma2(A_, u_.x, p0_.x);                                            \
            ffma2(B_, u_.y, p0_.y);                                            \
            ffma2(C_, u_.z, p1_.x);                                            \
            ffma2(D_, u_.w, p1_.y);                                            \
        }                                                                      \
        LOADW(W, midx[t + 3]);                                                 \
        A_ = addx2(A_, B_);                                                    \
        C_ = addx2(C_, D_);                                                    \
        A_ = addx2(A_, C_);                                                    \
        float lo_, hi_;                                                        \
        unpack2(A_, lo_, hi_);                                                 \
        psm[(t + 1) & 1][j] = lo_ + hi_;                                       \
        asm volatile("bar.sync %0, 64;" :: "r"(barid) : "memory");             \
        t++;                                                                   \
    }

__device__ __forceinline__ void run_dir(const uint4* __restrict__ pairs,
                                        const uint4* __restrict__ singles,
                                        const int* midx, int nsteps,
                                        float (*psm)[QN], int j, int barid) {
    uint4 w0[8], w1[8], w2[8];
    LOADW(w0, midx[0]);
    LOADW(w1, midx[1]);
    LOADW(w2, midx[2]);
    int t = 0;
    while (t < nsteps) {
        STEPD(w0);
        if (t >= nsteps) break;
        STEPD(w1);
        if (t >= nsteps) break;
        STEPD(w2);
    }
}

__global__ void __launch_bounds__(256, 1)
k_forward(const int* __restrict__ x, const int* __restrict__ lengths,
          const float* __restrict__ f_logits, float* __restrict__ out) {
    __shared__ __align__(16) float pL[2][2][QN];   // [slot][buf][col]
    __shared__ __align__(16) float pR[2][2][QN];
    __shared__ __align__(16) float ef[QN];         // exp(f - M)
    __shared__ int midxA[2][MAXSTEP + 3];          // [slot] left  (padded x3)
    __shared__ int midxB[2][MAXSTEP + 3];          // [slot] right (padded x3)
    __shared__ float red[2][4];
    __shared__ float prep[4];
    __shared__ float sLogS2;

    int tid = threadIdx.x;

    // ---- hoisted f_logits prep (warps 0-1) ----
    if (tid < 64) {
        float f = __ldg(f_logits + tid);
        float Mv = f;
#pragma unroll
        for (int o = 16; o; o >>= 1) Mv = fmaxf(Mv, __shfl_xor_sync(0xFFFFFFFFu, Mv, o));
        if ((tid & 31) == 0) prep[tid >> 5] = Mv;
        asm volatile("bar.sync 7, 64;" ::: "memory");
        float M = fmaxf(prep[0], prep[1]);
        float e = expf(f - M);
        ef[tid] = e;
        float S2 = e;
#pragma unroll
        for (int o = 16; o; o >>= 1) S2 += __shfl_xor_sync(0xFFFFFFFFu, S2, o);
        if ((tid & 31) == 0) prep[2 + (tid >> 5)] = S2;
        asm volatile("bar.sync 7, 64;" ::: "memory");
        if (tid == 0) sLogS2 = logf(prep[2] + prep[3]);
    }
    __syncthreads();

    // ---- static assignment: slot0 = rank cta (long), slot1 = rank 255-cta ----
    int slot = tid >> 7;            // 0 or 1
    int tid7 = tid & 127;           // id within sequence group
    int cta = blockIdx.x;
    int rank = slot == 0 ? cta : (BN - 1 - cta);
    if (slot == 1 && rank < 148) return;          // no second sequence
    int b = g_order[rank];

    int L = __ldg(lengths + b);
    int np  = L >> 1;
    int nL  = (np + 1) >> 1;
    int npR = np - nL;
    int odd = L & 1;
    int nR  = npR + odd;
    int m = 2 * nL;
    const int* xb = x + b * SN;
    int* midxL = midxA[slot];
    int* midxR = midxB[slot];

    for (int t = tid7; t < nL; t += 128)
        midxL[t] = (__ldg(xb + 2 * t) * 32 + __ldg(xb + 2 * t + 1)) * 4096;
    for (int s2 = tid7; s2 < nR; s2 += 128) {
        int off;
        if (odd && s2 == 0) {
            off = __ldg(xb + L - 1) * 4096 | 1;
        } else {
            int k = npR - 1 - (s2 - odd);
            off = (__ldg(xb + m + 2 * k) * 32 + __ldg(xb + m + 2 * k + 1)) * 4096;
        }
        midxR[s2] = off;
    }
    if (tid7 < 3) {                                // pad for branchless prefetch
        midxL[nL + tid7] = 0;
        midxR[nR + tid7] = 0;
    }
    if (tid7 < 64) pL[slot][0][tid7] = (tid7 == 0) ? 1.0f : 0.0f;
    else           pR[slot][0][tid7 - 64] = ef[tid7 - 64];
    asm volatile("bar.sync %0, 128;" :: "r"(5 + slot) : "memory");

    int dir = tid7 >> 6;            // 0 = left, 1 = right
    int barid = 1 + 2 * slot + dir; // 1,2 (slot0), 3,4 (slot1)
    if (dir == 0)
        run_dir((const uint4*)g_pairs,  (const uint4*)g_singles,  midxL, nL,
                pL[slot], tid7, barid);
    else
        run_dir((const uint4*)g_pairsT, (const uint4*)g_singlesT, midxR, nR,
                pR[slot], tid7 - 64, barid);
    asm volatile("bar.sync %0, 128;" :: "r"(5 + slot) : "memory");

    // ---- combine (left group of each slot) ----
    if (tid7 < 64) {
        int wid = tid7 >> 5;
        float a = pL[slot][nL & 1][tid7];
        float r = pR[slot][nR & 1][tid7];
        float d = a * r, sa = a;
#pragma unroll
        for (int o = 16; o; o >>= 1) {
            d  += __shfl_xor_sync(0xFFFFFFFFu, d,  o);
            sa += __shfl_xor_sync(0xFFFFFFFFu, sa, o);
        }
        if ((tid7 & 31) == 0) { red[slot][wid] = d; red[slot][2 + wid] = sa; }
        asm volatile("bar.sync %0, 64;" :: "r"(1 + 2 * slot) : "memory");
        if (tid7 == 0)
            out[b] = logf(red[slot][0] + red[slot][1])
                   - logf(red[slot][2] + red[slot][3]) - sLogS2;
    }
}

extern "C" void kernel_launch(void* const* d_in, const int* in_sizes, int n_in,
                              void* d_out, int out_size) {
    const int*   x        = (const int*)d_in[0];       // [256, 2048]
    const int*   lengths  = (const int*)d_in[1];       // [256]
    const float* T_logits = (const float*)d_in[2];     // [64, 32, 64]
    const float* f_logits = (const float*)d_in[3];     // [64]
    float* out = (float*)d_out;                        // [256]

    k_softmax<<<512, 128>>>(T_logits);
    k_sort<<<1, BN>>>(lengths);
    k_pairs<<<1024, 128>>>();
    k_forward<<<148, 256>>>(x, lengths, f_logits, out);
}

// round 12
// speedup vs baseline: 1.4391x; 1.0057x over previous
#include <cuda_runtime.h>
#include <cuda_bf16.h>

#define QN 64
#define AN 32
#define BN 256
#define SN 2048
#define MAXSTEP 520
#define NMAT 1056   // 1024 pair matrices + 32 singles

// Interleaved bf16 layout for a 64x64 matrix W: element (i,j) at
//   bf16 index  (i>>3)*512 + j*8 + (i&7)
// One 16B granule = rows 8c..8c+7 of column j. Granule index within a
// matrix = c*64 + j. Matrix m starts at granule m*512.
// Pairs are ids 0..1023 (a0*32+a1); singles are ids 1024+a.
__device__ __align__(16) static __nv_bfloat16 g_tab [NMAT * 4096];  // W, 8.6 MB
__device__ __align__(16) static __nv_bfloat16 g_tabT[NMAT * 4096];  // W^T
__device__ __align__(16) static float g_Wf[32 * 4096];              // f32 W[a]
__device__ static short g_order[BN];                                // ids, desc len

// ---------------------------------------------------------------------------
// Kernel 1: W[a][i][j] = softmax_j(T_logits[i][a][:]). One warp per (i,a).
// ---------------------------------------------------------------------------
__global__ void k_softmax(const float* __restrict__ T) {
    int warp = (blockIdx.x << 2) + (threadIdx.x >> 5);   // warp = i*32 + a
    int lane = threadIdx.x & 31;
    int i = warp >> 5, a = warp & 31;
    const float* row = T + warp * 64;
    float v0 = row[lane], v1 = row[lane + 32];
    float m = fmaxf(v0, v1);
#pragma unroll
    for (int o = 16; o; o >>= 1) m = fmaxf(m, __shfl_xor_sync(0xFFFFFFFFu, m, o));
    float e0 = expf(v0 - m), e1 = expf(v1 - m);
    float s = e0 + e1;
#pragma unroll
    for (int o = 16; o; o >>= 1) s += __shfl_xor_sync(0xFFFFFFFFu, s, o);
    float inv = 1.0f / s;
    float w0 = e0 * inv, w1 = e1 * inv;

    float* wf = g_Wf + a * 4096 + i * 64;
    wf[lane] = w0;
    wf[lane + 32] = w1;

    __nv_bfloat16* sg  = g_tab  + (1024 + a) * 4096;
    __nv_bfloat16* sgT = g_tabT + (1024 + a) * 4096;
    int c = i >> 3, r = i & 7;
    int j0 = lane, j1 = lane + 32;
    sg[c * 512 + j0 * 8 + r] = __float2bfloat16(w0);
    sg[c * 512 + j1 * 8 + r] = __float2bfloat16(w1);
    sgT[(j0 >> 3) * 512 + i * 8 + (j0 & 7)] = __float2bfloat16(w0);
    sgT[(j1 >> 3) * 512 + i * 8 + (j1 & 7)] = __float2bfloat16(w1);
}

// ---------------------------------------------------------------------------
// Kernel 1b: rank-sort sequence ids by length descending.
// ---------------------------------------------------------------------------
__global__ void k_sort(const int* __restrict__ lengths) {
    __shared__ int Ls[BN];
    int t = threadIdx.x;
    int L = lengths[t];
    Ls[t] = L;
    __syncthreads();
    int rank = 0;
#pragma unroll 8
    for (int i = 0; i < BN; i++) {
        int Li = Ls[i];
        rank += (Li > L) || (Li == L && i < t);
    }
    g_order[rank] = (short)t;
}

// ---------------------------------------------------------------------------
// Kernel 2: P = W[a0]@W[a1]; writes bf16 interleaved P AND P^T into g_tab/T.
// 1024 CTAs x 128 threads, 8x4 register tiles, smem round-trip for transpose.
// ---------------------------------------------------------------------------
__device__ __forceinline__ unsigned packbf(float a, float b) {
    __nv_bfloat162 h = __floats2bfloat162_rn(a, b);
    return *(unsigned*)&h;
}

__global__ void k_pairs() {
    __shared__ __align__(16) float As[64][68];   // As[k][i] = A[i][k]; reused Out[i][j]
    __shared__ __align__(16) float Bs[64][64];   // Bs[k][j] = B[k][j]
    int mId = blockIdx.x;
    int a0 = mId >> 5, a1 = mId & 31;
    const float* A  = g_Wf + a0 * 4096;
    const float* Bm = g_Wf + a1 * 4096;
    int t = threadIdx.x;
    for (int idx = t; idx < 4096; idx += 128) {
        As[idx & 63][idx >> 6] = A[idx];
        Bs[idx >> 6][idx & 63] = Bm[idx];
    }
    __syncthreads();

    int i0 = (t >> 4) << 3, j0 = (t & 15) << 2;   // 8 rows x 4 cols per thread
    float acc[8][4];
#pragma unroll
    for (int r = 0; r < 8; r++)
#pragma unroll
        for (int c = 0; c < 4; c++) acc[r][c] = 0.f;

    for (int k = 0; k < 64; k++) {
        float av[8];
        *(float4*)(av)     = *(const float4*)&As[k][i0];
        *(float4*)(av + 4) = *(const float4*)&As[k][i0 + 4];
        float4 bv = *(const float4*)&Bs[k][j0];
#pragma unroll
        for (int r = 0; r < 8; r++) {
            acc[r][0] = fmaf(av[r], bv.x, acc[r][0]);
            acc[r][1] = fmaf(av[r], bv.y, acc[r][1]);
            acc[r][2] = fmaf(av[r], bv.z, acc[r][2]);
            acc[r][3] = fmaf(av[r], bv.w, acc[r][3]);
        }
    }
    __syncthreads();
#pragma unroll
    for (int r = 0; r < 8; r++)
#pragma unroll
        for (int c = 0; c < 4; c++) As[i0 + r][j0 + c] = acc[r][c];
    __syncthreads();

    __nv_bfloat16* dstN = g_tab  + mId * 4096;
    __nv_bfloat16* dstT = g_tabT + mId * 4096;
#pragma unroll
    for (int q = 0; q < 4; q++) {
        int g = t + 128 * q;              // granule id 0..511
        int c = g >> 6, j = g & 63;
        uint4 u;
        u.x = packbf(As[8 * c + 0][j], As[8 * c + 1][j]);
        u.y = packbf(As[8 * c + 2][j], As[8 * c + 3][j]);
        u.z = packbf(As[8 * c + 4][j], As[8 * c + 5][j]);
        u.w = packbf(As[8 * c + 6][j], As[8 * c + 7][j]);
        *(uint4*)(dstN + c * 512 + j * 8) = u;
        int i = g & 63, cT = g >> 6;
        const float* rp = &As[i][8 * cT];
        uint4 v;
        v.x = packbf(rp[0], rp[1]);
        v.y = packbf(rp[2], rp[3]);
        v.z = packbf(rp[4], rp[5]);
        v.w = packbf(rp[6], rp[7]);
        *(uint4*)(dstT + cT * 512 + i * 8) = v;
    }
}

// ---------------------------------------------------------------------------
// Kernel 3: bidirectional forward, 2 sequences per CTA (long<->short static
// pairing). 148 CTAs x 256 threads = 4 independent 64-thread groups:
//   tid   0- 63: seqA left (bar1)   tid  64-127: seqA right (bar2)
//   tid 128-191: seqB left (bar3)   tid 192-255: seqB right (bar4)
// One thread per column. Balanced scalar math: per u32 of W, shl+and (alu)
// then 2 scalar FFMA (fma pipe) -> dual-pipe ~1 instr/cyc for a solo warp.
// midx stores GRANULE offsets into the merged table (no select, no branch).
// Depth-3 register prefetch + 3-entry midx padding = branchless.
// ---------------------------------------------------------------------------
#define LOADW(W, MIDX)                                                         \
    {                                                                          \
        const uint4* b_ = tab + (MIDX) + j;                                    \
        _Pragma("unroll")                                                      \
        for (int c_ = 0; c_ < 8; c_++) (W)[c_] = __ldg(b_ + c_ * 64);          \
    }

#define STEPD(W)                                                               \
    {                                                                          \
        const float4* pc_ = (const float4*)psm[t & 1];                         \
        float a0_ = 0.f, a1_ = 0.f, a2_ = 0.f, a3_ = 0.f;                      \
        float a4_ = 0.f, a5_ = 0.f, a6_ = 0.f, a7_ = 0.f;                      \
        _Pragma("unroll")                                                      \
        for (int c_ = 0; c_ < 8; c_++) {                                       \
            float4 pa_ = pc_[2 * c_];                                          \
            float4 pb_ = pc_[2 * c_ + 1];                                      \
            uint4 u_ = (W)[c_];                                                \
            a0_ = fmaf(__uint_as_float(u_.x << 16),          pa_.x, a0_);      \
            a1_ = fmaf(__uint_as_float(u_.x & 0xFFFF0000u),  pa_.y, a1_);      \
            a2_ = fmaf(__uint_as_float(u_.y << 16),          pa_.z, a2_);      \
            a3_ = fmaf(__uint_as_float(u_.y & 0xFFFF0000u),  pa_.w, a3_);      \
            a4_ = fmaf(__uint_as_float(u_.z << 16),          pb_.x, a4_);      \
            a5_ = fmaf(__uint_as_float(u_.z & 0xFFFF0000u),  pb_.y, a5_);      \
            a6_ = fmaf(__uint_as_float(u_.w << 16),          pb_.z, a6_);      \
            a7_ = fmaf(__uint_as_float(u_.w & 0xFFFF0000u),  pb_.w, a7_);      \
        }                                                                      \
        LOADW(W, midx[t + 3]);                                                 \
        psm[(t + 1) & 1][j] = ((a0_ + a1_) + (a2_ + a3_))                      \
                            + ((a4_ + a5_) + (a6_ + a7_));                     \
        asm volatile("bar.sync %0, 64;" :: "r"(barid) : "memory");             \
        t++;                                                                   \
    }

__device__ __forceinline__ void run_dir(const uint4* __restrict__ tab,
                                        const int* midx, int nsteps,
                                        float (*psm)[QN], int j, int barid) {
    uint4 w0[8], w1[8], w2[8];
    LOADW(w0, midx[0]);
    LOADW(w1, midx[1]);
    LOADW(w2, midx[2]);
    int t = 0;
    while (t < nsteps) {
        STEPD(w0);
        if (t >= nsteps) break;
        STEPD(w1);
        if (t >= nsteps) break;
        STEPD(w2);
    }
}

__global__ void __launch_bounds__(256, 1)
k_forward(const int* __restrict__ x, const int* __restrict__ lengths,
          const float* __restrict__ f_logits, float* __restrict__ out) {
    __shared__ __align__(16) float pL[2][2][QN];   // [slot][buf][col]
    __shared__ __align__(16) float pR[2][2][QN];
    __shared__ __align__(16) float ef[QN];         // exp(f - M)
    __shared__ int midxA[2][MAXSTEP + 3];          // [slot] left  (padded x3)
    __shared__ int midxB[2][MAXSTEP + 3];          // [slot] right (padded x3)
    __shared__ float red[2][4];
    __shared__ float prep[4];
    __shared__ float sLogS2;

    int tid = threadIdx.x;

    // ---- hoisted f_logits prep (warps 0-1) ----
    if (tid < 64) {
        float f = __ldg(f_logits + tid);
        float Mv = f;
#pragma unroll
        for (int o = 16; o; o >>= 1) Mv = fmaxf(Mv, __shfl_xor_sync(0xFFFFFFFFu, Mv, o));
        if ((tid & 31) == 0) prep[tid >> 5] = Mv;
        asm volatile("bar.sync 7, 64;" ::: "memory");
        float M = fmaxf(prep[0], prep[1]);
        float e = expf(f - M);
        ef[tid] = e;
        float S2 = e;
#pragma unroll
        for (int o = 16; o; o >>= 1) S2 += __shfl_xor_sync(0xFFFFFFFFu, S2, o);
        if ((tid & 31) == 0) prep[2 + (tid >> 5)] = S2;
        asm volatile("bar.sync 7, 64;" ::: "memory");
        if (tid == 0) sLogS2 = logf(prep[2] + prep[3]);
    }
    __syncthreads();

    // ---- static assignment: slot0 = rank cta (long), slot1 = rank 255-cta ----
    int slot = tid >> 7;            // 0 or 1
    int tid7 = tid & 127;           // id within sequence group
    int cta = blockIdx.x;
    int rank = slot == 0 ? cta : (BN - 1 - cta);
    if (slot == 1 && rank < 148) return;          // no second sequence
    int b = g_order[rank];

    int L = __ldg(lengths + b);
    int np  = L >> 1;
    int nL  = (np + 1) >> 1;
    int npR = np - nL;
    int odd = L & 1;
    int nR  = npR + odd;
    int m = 2 * nL;
    const int* xb = x + b * SN;
    int* midxL = midxA[slot];
    int* midxR = midxB[slot];

    // midx in GRANULE units: pair id (a0*32+a1)*512; single id (1024+a)*512.
    for (int t = tid7; t < nL; t += 128)
        midxL[t] = (__ldg(xb + 2 * t) * 32 + __ldg(xb + 2 * t + 1)) * 512;
    for (int s2 = tid7; s2 < nR; s2 += 128) {
        int off;
        if (odd && s2 == 0) {
            off = (1024 + __ldg(xb + L - 1)) * 512;
        } else {
            int k = npR - 1 - (s2 - odd);
            off = (__ldg(xb + m + 2 * k) * 32 + __ldg(xb + m + 2 * k + 1)) * 512;
        }
        midxR[s2] = off;
    }
    if (tid7 < 3) {                                // pad for branchless prefetch
        midxL[nL + tid7] = 0;
        midxR[nR + tid7] = 0;
    }
    if (tid7 < 64) pL[slot][0][tid7] = (tid7 == 0) ? 1.0f : 0.0f;
    else           pR[slot][0][tid7 - 64] = ef[tid7 - 64];
    asm volatile("bar.sync %0, 128;" :: "r"(5 + slot) : "memory");

    int dir = tid7 >> 6;            // 0 = left, 1 = right
    int barid = 1 + 2 * slot + dir; // 1,2 (slot0), 3,4 (slot1)
    if (dir == 0)
        run_dir((const uint4*)g_tab,  midxL, nL, pL[slot], tid7, barid);
    else
        run_dir((const uint4*)g_tabT, midxR, nR, pR[slot], tid7 - 64, barid);
    asm volatile("bar.sync %0, 128;" :: "r"(5 + slot) : "memory");

    // ---- combine (left group of each slot) ----
    if (tid7 < 64) {
        int wid = tid7 >> 5;
        float a = pL[slot][nL & 1][tid7];
        float r = pR[slot][nR & 1][tid7];
        float d = a * r, sa = a;
#pragma unroll
        for (int o = 16; o; o >>= 1) {
            d  += __shfl_xor_sync(0xFFFFFFFFu, d,  o);
            sa += __shfl_xor_sync(0xFFFFFFFFu, sa, o);
        }
        if ((tid7 & 31) == 0) { red[slot][wid] = d; red[slot][2 + wid] = sa; }
        asm volatile("bar.sync %0, 64;" :: "r"(1 + 2 * slot) : "memory");
        if (tid7 == 0)
            out[b] = logf(red[slot][0] + red[slot][1])
                   - logf(red[slot][2] + red[slot][3]) - sLogS2;
    }
}

extern "C" void kernel_launch(void* const* d_in, const int* in_sizes, int n_in,
                              void* d_out, int out_size) {
    const int*   x        = (const int*)d_in[0];       // [256, 2048]
    const int*   lengths  = (const int*)d_in[1];       // [256]
    const float* T_logits = (const float*)d_in[2];     // [64, 32, 64]
    const float* f_logits = (const float*)d_in[3];     // [64]
    float* out = (float*)d_out;                        // [256]

    k_softmax<<<512, 128>>>(T_logits);
    k_sort<<<1, BN>>>(lengths);
    k_pairs<<<1024, 128>>>();
    k_forward<<<148, 256>>>(x, lengths, f_logits, out);
}